// round 7
// baseline (speedup 1.0000x reference)
#include <cuda_runtime.h>

// NeighborSample: x (8,64,64,192) f32 -> out (8*64*64, 5, 5, 192) f32
// out[pix][i][j][k] = x[b][y+i-2][x+j-2][k] (zero-padded)
//
// Persistent smem-tiled kernel. Tile = (one y row, 16 x-pixels, 64-float
// channel chunk). Grid is sized to exactly one resident wave (148 SMs x 8
// blocks); each block loops over ~5.2 tiles, eliminating wave-quantization
// tail (6144/1184 = 5.19 waves in the non-persistent version).

#define TX      16u           // pixels per tile (x)
#define CCH     16u           // float4 per channel chunk (64 floats)
#define SROWS   5u
#define SCOLS   20u           // TX + 4 halo
#define SSTRIDE 17u           // CCH + 1 pad (bank-conflict avoidance)
#define SMEM_F4 (SROWS * SCOLS * SSTRIDE)   // 1700 float4 = 27.2 KB
#define NTILES  6144u         // b(8) * y(64) * xtiles(4) * cchunks(3)
#define GRID    1184u         // 148 SMs * 8 resident blocks

__global__ void __launch_bounds__(256, 8) neighbor_sample_persist(
    const float4* __restrict__ in, float4* __restrict__ out)
{
    __shared__ float4 s[SMEM_F4];
    unsigned tid = threadIdx.x;

    for (unsigned bx = blockIdx.x; bx < NTILES; bx += GRID) {
        // tile decode: bx = ((b*64 + y)*4 + xt)*3 + cc
        unsigned cc = bx % 3u;
        unsigned t1 = bx / 3u;
        unsigned xt = t1 & 3u;
        unsigned t2 = t1 >> 2;
        unsigned y  = t2 & 63u;
        unsigned b  = t2 >> 6;
        unsigned x0 = xt * TX;
        unsigned c0 = cc * CCH;

        __syncthreads();   // previous tile's smem reads must finish

        // ---- load phase: 5 x 20 x 16 float4 = 1600 elems, zeros in halo ----
        for (unsigned l = tid; l < SROWS * SCOLS * CCH; l += 256u) {
            unsigned k4  = l & 15u;
            unsigned cl  = l >> 4;        // 0..99
            unsigned col = cl % SCOLS;
            unsigned row = cl / SCOLS;
            int gx = (int)(x0 + col) - 2;
            int gy = (int)(y + row) - 2;
            float4 v = make_float4(0.f, 0.f, 0.f, 0.f);
            if ((unsigned)gx < 64u && (unsigned)gy < 64u) {
                unsigned src = ((((b << 6) + (unsigned)gy) << 6) | (unsigned)gx) * 48u
                             + c0 + k4;
                v = __ldg(&in[src]);
            }
            s[(row * SCOLS + col) * SSTRIDE + k4] = v;
        }
        __syncthreads();

        // ---- store phase: warp = 2 contiguous 256B runs = 4 full 128B lines ----
        unsigned k4  = tid & 15u;
        unsigned px  = tid >> 4;                       // 0..15
        unsigned pix = (((b << 6) + y) << 6) + x0 + px;
        unsigned o   = pix * 1200u + c0 + k4;          // (pix*25*48) float4
        unsigned sb  = px * SSTRIDE + k4;

        #pragma unroll
        for (unsigned i = 0; i < 5u; i++) {
            #pragma unroll
            for (unsigned j = 0; j < 5u; j++) {
                float4 v = s[sb + (i * SCOLS + j) * SSTRIDE];
                __stcs(&out[o], v);   // streaming store: don't pollute L2
                o += 48u;
            }
        }
    }
}

extern "C" void kernel_launch(void* const* d_in, const int* in_sizes, int n_in,
                              void* d_out, int out_size)
{
    const float4* in  = (const float4*)d_in[0];
    float4*       out = (float4*)d_out;
    neighbor_sample_persist<<<GRID, 256>>>(in, out);
}

// round 10
// speedup vs baseline: 1.0026x; 1.0026x over previous
#include <cuda_runtime.h>
#include <cstdint>

// NeighborSample: x (8,64,64,192) f32 -> out (8*64*64, 5, 5, 192) f32
// out[pix][i][j][k] = x[b][y+i-2][x+j-2][k] (zero-padded)
//
// Per-pixel TMA bulk store: each pixel's output block is 25*192*4 = 19200
// contiguous bytes. A block assembles it in smem (LDG gather from the
// L2-resident 25MB input) and issues ONE cp.async.bulk shared->global per
// pixel. Double-buffered smem + bulk_group pipelining overlaps gather(p+1)
// with store(p). Stores never touch L1/LSU; DRAM sees 19.2KB sequential bursts.

#define PIX_PER_BLK 4u
#define PF4         1200u           // float4 per pixel output (25*48)
#define PBYTES      19200u

__global__ void __launch_bounds__(256) neighbor_sample_tma(
    const float4* __restrict__ in, float4* __restrict__ out)
{
    __shared__ float4 buf[2][PF4];   // 2 x 19.2KB = 38.4KB
    unsigned tid = threadIdx.x;

    #pragma unroll
    for (unsigned p = 0; p < PIX_PER_BLK; p++) {
        unsigned pix  = blockIdx.x * PIX_PER_BLK + p;
        unsigned bsel = p & 1u;

        if (p >= 2u) {
            // recycle buffer bsel: allow at most 1 group (the other buffer) in flight
            if (tid == 0u)
                asm volatile("cp.async.bulk.wait_group 1;" ::: "memory");
            __syncthreads();
        }

        unsigned xcol = pix & 63u;
        unsigned yrow = (pix >> 6) & 63u;
        unsigned b    = pix >> 12;

        // gather this pixel's 25 x 48 float4 into smem (zeros at borders)
        for (unsigned l = tid; l < PF4; l += 256u) {
            unsigned k4  = l % 48u;
            unsigned seg = l / 48u;          // 0..24
            unsigned j   = seg % 5u;
            unsigned i   = seg / 5u;
            int sy = (int)(yrow + i) - 2;
            int sx = (int)(xcol + j) - 2;
            float4 v = make_float4(0.f, 0.f, 0.f, 0.f);
            if ((unsigned)sy < 64u && (unsigned)sx < 64u) {
                unsigned src = ((((b << 6) + (unsigned)sy) << 6) | (unsigned)sx) * 48u + k4;
                v = __ldg(&in[src]);
            }
            buf[bsel][l] = v;
        }
        __syncthreads();

        if (tid == 0u) {
            // order generic-proxy smem writes before async-proxy bulk read
            asm volatile("fence.proxy.async.shared::cta;" ::: "memory");
            uint32_t saddr = (uint32_t)__cvta_generic_to_shared(&buf[bsel][0]);
            const float4* gptr = out + (size_t)pix * PF4;
            asm volatile(
                "cp.async.bulk.global.shared::cta.bulk_group [%0], [%1], %2;"
                :: "l"(gptr), "r"(saddr), "r"(PBYTES) : "memory");
            asm volatile("cp.async.bulk.commit_group;" ::: "memory");
        }
    }

    // CTA must not retire with bulk stores reading its smem
    if (tid == 0u)
        asm volatile("cp.async.bulk.wait_group 0;" ::: "memory");
}

extern "C" void kernel_launch(void* const* d_in, const int* in_sizes, int n_in,
                              void* d_out, int out_size)
{
    const float4* in  = (const float4*)d_in[0];
    float4*       out = (float4*)d_out;
    // 32768 pixels / 4 per block = 8192 blocks (~11 waves at 5 blocks/SM)
    neighbor_sample_tma<<<8192, 256>>>(in, out);
}

// round 13
// speedup vs baseline: 1.1559x; 1.1528x over previous
#include <cuda_runtime.h>

// NeighborSample: x (8,64,64,192) f32 -> out (8*64*64, 5, 5, 192) f32
// out[pix][i][j][k] = x[b][y+i-2][x+j-2][k] (zero-padded)
//
// Flat coalesced mapping (round-4 champion) + ILP=4: each thread handles 4
// float4 at stride blockDim, so each block writes 1024 consecutive float4
// (16KB contiguous) and each thread keeps 4 independent LDG->STG chains in
// flight (MLP=4). Every LDG/STG instruction is fully coalesced (512B/warp).

#define C4    48u                      // 192 floats / 4
#define N4    39321600u                // 32768 * 25 * 48
#define ILP   4u
#define TPB   256u
#define GRID  (N4 / (ILP * TPB))       // 38400, exact

__global__ void __launch_bounds__(TPB) neighbor_sample_ilp4(
    const float4* __restrict__ in, float4* __restrict__ out)
{
    unsigned base = blockIdx.x * (ILP * TPB) + threadIdx.x;

    float4 v[ILP];

    // ---- gather: 4 independent decode+LDG chains, loads issue back-to-back ----
    #pragma unroll
    for (unsigned u = 0; u < ILP; u++) {
        unsigned idx = base + u * TPB;

        // decode: idx = (pix*25 + ij)*48 + k4
        unsigned k4  = idx % C4;
        unsigned r   = idx / C4;
        unsigned ij  = r % 25u;
        unsigned pix = r / 25u;
        unsigned j   = ij % 5u;
        unsigned i   = ij / 5u;

        unsigned xcol = pix & 63u;
        unsigned yrow = (pix >> 6) & 63u;
        unsigned b    = pix >> 12;

        int sy = (int)(yrow + i) - 2;
        int sx = (int)(xcol + j) - 2;

        v[u] = make_float4(0.f, 0.f, 0.f, 0.f);
        if ((unsigned)sy < 64u && (unsigned)sx < 64u) {
            unsigned src = ((((b << 6) + (unsigned)sy) << 6) | (unsigned)sx) * C4 + k4;
            v[u] = __ldg(&in[src]);
        }
    }

    // ---- store: 4 coalesced streaming stores, 16KB contiguous per block ----
    #pragma unroll
    for (unsigned u = 0; u < ILP; u++) {
        __stcs(&out[base + u * TPB], v[u]);
    }
}

extern "C" void kernel_launch(void* const* d_in, const int* in_sizes, int n_in,
                              void* d_out, int out_size)
{
    const float4* in  = (const float4*)d_in[0];
    float4*       out = (float4*)d_out;
    neighbor_sample_ilp4<<<GRID, TPB>>>(in, out);
}